// round 5
// baseline (speedup 1.0000x reference)
#include <cuda_runtime.h>
#include <cstdint>

#define Nn 100000
#define Ee 1600000
#define Dd 128
#define Hh 8
#define FF 512

typedef unsigned long long u64;

// ---------------- scratch (device globals; no allocs allowed) ----------------
__device__ float g_h[Nn * Dd];        // LN1 output
__device__ float g_feat0[Nn * Dd];    // initial feat (GEMM1 out); later rst
__device__ float g_fA[Nn * Dd];       // ping ; later x (LN2 out)
__device__ float g_fB[Nn * Dd];       // pong
__device__ float g_hidden[Nn * FF];   // FFN hidden
__device__ float g_eh[Nn * Hh];
__device__ float g_et[Nn * Hh];
__device__ float g_acsr[Ee * Hh];     // normalized attention, CSR order
__device__ int   g_srccsr[Ee];        // src node per CSR slot
__device__ int   g_csredge[Ee];       // original edge id per CSR slot
__device__ int   g_cnt[Nn];
__device__ int   g_rowptr[Nn + 1];
__device__ int   g_wptr[Nn];
__device__ int   g_bsum[128];

__device__ __forceinline__ float* gbuf(int i) {
    switch (i) {
        case 0: return g_h;
        case 1: return g_feat0;
        case 2: return g_fA;
        case 3: return g_fB;
        case 4: return g_hidden;
    }
    return nullptr;
}

__device__ __forceinline__ void mma_tf32(float& c0, float& c1, float& c2, float& c3,
                                         uint32_t a0, uint32_t a1, uint32_t a2, uint32_t a3,
                                         uint32_t b0, uint32_t b1) {
    asm volatile(
        "mma.sync.aligned.m16n8k8.row.col.f32.tf32.tf32.f32 "
        "{%0,%1,%2,%3}, {%4,%5,%6,%7}, {%8,%9}, {%0,%1,%2,%3};"
        : "+f"(c0), "+f"(c1), "+f"(c2), "+f"(c3)
        : "r"(a0), "r"(a1), "r"(a2), "r"(a3), "r"(b0), "r"(b1));
}

__device__ __forceinline__ void cpasync16(uint32_t s, const void* g, int sz) {
    asm volatile("cp.async.ca.shared.global [%0], [%1], 16, %2;"
                 :: "r"(s), "l"(g), "r"(sz) : "memory");
}
#define CP_COMMIT() asm volatile("cp.async.commit_group;" ::: "memory")
#define CP_WAIT1() asm volatile("cp.async.wait_group 1;" ::: "memory")
#define CP_WAIT0() asm volatile("cp.async.wait_group 0;" ::: "memory")

// swizzled float index into a [128][16] tile (xor on col bits 2..3)
__device__ __forceinline__ int swz(int row, int col) {
    return (row << 4) | (col ^ ((row & 3) << 2));
}

// ---------------- tf32 mma.sync GEMM + cp.async double buffer ----------------
// C[rows x M] = A[rows x K] * B[M x K]^T
// mode 0: plain   mode 1: relu(x + bias)   mode 2: x + bias + add
__global__ void __launch_bounds__(256) mgemm_kernel(int Ai, const float* __restrict__ B,
                                                    const float* __restrict__ bias,
                                                    int Addi, int Ci, float* __restrict__ Cext,
                                                    int M, int K, int mode) {
    __shared__ float As[2][128 * 16];
    __shared__ float Bs[2][128 * 16];
    const float* A = gbuf(Ai);
    float* C = (Ci >= 0) ? gbuf(Ci) : Cext;
    const float* add = (Addi >= 0) ? gbuf(Addi) : nullptr;

    int bm = blockIdx.y * 128;
    int bn = blockIdx.x * 128;
    int tid = threadIdx.x;
    int wid = tid >> 5, lane = tid & 31;
    int g = lane >> 2, t4 = lane & 3;
    int warpM = wid & 3, warpN = wid >> 2;   // 4 x 2 warps

    float acc[2][8][4];
    #pragma unroll
    for (int i = 0; i < 2; i++)
        #pragma unroll
        for (int j = 0; j < 8; j++)
            #pragma unroll
            for (int q = 0; q < 4; q++) acc[i][j][q] = 0.0f;

    // copy mapping: thread -> (row, 8-float half)
    int crow = tid >> 1;
    int c0 = (tid & 1) * 8;
    bool aval = (bm + crow) < Nn;
    const float* agp = A + (size_t)(aval ? (bm + crow) : 0) * K + c0;
    const float* bgp = B + (size_t)(bn + crow) * K + c0;
    int asz = aval ? 16 : 0;

    uint32_t sA = (uint32_t)__cvta_generic_to_shared(As);
    uint32_t sB = (uint32_t)__cvta_generic_to_shared(Bs);
    uint32_t dA0 = sA + (uint32_t)swz(crow, c0) * 4u;
    uint32_t dA1 = sA + (uint32_t)swz(crow, c0 + 4) * 4u;
    uint32_t dB0 = sB + (uint32_t)swz(crow, c0) * 4u;
    uint32_t dB1 = sB + (uint32_t)swz(crow, c0 + 4) * 4u;

    const int nit = K >> 4;
    // prologue: stage 0
    {
        cpasync16(dA0, agp, asz);
        cpasync16(dA1, agp + 4, asz);
        cpasync16(dB0, bgp, 16);
        cpasync16(dB1, bgp + 4, 16);
        CP_COMMIT();
    }

    for (int i = 0; i < nit; i++) {
        if (i + 1 < nit) {
            uint32_t boff = ((i + 1) & 1) * (128 * 16 * 4);
            int kk = (i + 1) << 4;
            cpasync16(dA0 + boff, agp + kk, asz);
            cpasync16(dA1 + boff, agp + kk + 4, asz);
            cpasync16(dB0 + boff, bgp + kk, 16);
            cpasync16(dB1 + boff, bgp + kk + 4, 16);
            CP_COMMIT();
            CP_WAIT1();
        } else {
            CP_WAIT0();
        }
        __syncthreads();
        const float* as = As[i & 1];
        const float* bs = Bs[i & 1];
        #pragma unroll
        for (int k0 = 0; k0 < 16; k0 += 8) {
            uint32_t af[2][4];
            #pragma unroll
            for (int mt = 0; mt < 2; mt++) {
                int m0 = warpM * 32 + mt * 16 + g;
                af[mt][0] = __float_as_uint(as[swz(m0, k0 + t4)]);
                af[mt][1] = __float_as_uint(as[swz(m0 + 8, k0 + t4)]);
                af[mt][2] = __float_as_uint(as[swz(m0, k0 + t4 + 4)]);
                af[mt][3] = __float_as_uint(as[swz(m0 + 8, k0 + t4 + 4)]);
            }
            uint32_t bf[8][2];
            #pragma unroll
            for (int nt = 0; nt < 8; nt++) {
                int n0 = warpN * 64 + nt * 8 + g;
                bf[nt][0] = __float_as_uint(bs[swz(n0, k0 + t4)]);
                bf[nt][1] = __float_as_uint(bs[swz(n0, k0 + t4 + 4)]);
            }
            #pragma unroll
            for (int mt = 0; mt < 2; mt++)
                #pragma unroll
                for (int nt = 0; nt < 8; nt++)
                    mma_tf32(acc[mt][nt][0], acc[mt][nt][1], acc[mt][nt][2], acc[mt][nt][3],
                             af[mt][0], af[mt][1], af[mt][2], af[mt][3],
                             bf[nt][0], bf[nt][1]);
        }
        __syncthreads();
    }

    // ---- epilogue: fragments -> C with fused bias/relu/add
    #pragma unroll
    for (int mt = 0; mt < 2; mt++) {
        int row0 = bm + warpM * 32 + mt * 16 + g;
        #pragma unroll
        for (int half = 0; half < 2; half++) {
            int row = row0 + half * 8;
            if (row >= Nn) continue;
            #pragma unroll
            for (int nt = 0; nt < 8; nt++) {
                int col = bn + warpN * 64 + nt * 8 + t4 * 2;
                float c0 = acc[mt][nt][half * 2];
                float c1 = acc[mt][nt][half * 2 + 1];
                if (mode >= 1) {
                    c0 += bias[col];
                    c1 += bias[col + 1];
                }
                if (mode == 1) {
                    c0 = fmaxf(c0, 0.f);
                    c1 = fmaxf(c1, 0.f);
                }
                if (mode == 2) {
                    const float* av = add + (size_t)row * M + col;
                    c0 += av[0];
                    c1 += av[1];
                }
                *(float2*)(C + (size_t)row * M + col) = make_float2(c0, c1);
            }
        }
    }
}

// ---------------- LN1: warp per row ----------------
__global__ void __launch_bounds__(256) ln1_kernel(const float* __restrict__ x,
                                                  const float* __restrict__ g,
                                                  const float* __restrict__ b) {
    int row = blockIdx.x * 8 + (threadIdx.x >> 5);
    if (row >= Nn) return;
    int lane = threadIdx.x & 31;
    float4 v = ((const float4*)(x + (size_t)row * Dd))[lane];
    float s  = v.x + v.y + v.z + v.w;
    float sq = v.x * v.x + v.y * v.y + v.z * v.z + v.w * v.w;
    #pragma unroll
    for (int o = 16; o; o >>= 1) {
        s  += __shfl_xor_sync(0xffffffffu, s, o);
        sq += __shfl_xor_sync(0xffffffffu, sq, o);
    }
    float mu  = s * (1.0f / Dd);
    float var = sq * (1.0f / Dd) - mu * mu;
    float inv = rsqrtf(var + 1e-5f);
    float4 gg = ((const float4*)g)[lane];
    float4 bb = ((const float4*)b)[lane];
    float4 o4;
    o4.x = (v.x - mu) * inv * gg.x + bb.x;
    o4.y = (v.y - mu) * inv * gg.y + bb.y;
    o4.z = (v.z - mu) * inv * gg.z + bb.z;
    o4.w = (v.w - mu) * inv * gg.w + bb.w;
    ((float4*)(g_h + (size_t)row * Dd))[lane] = o4;
}

// ---------------- rst = feat_final + h ; x = LN2(rst) ----------------
__global__ void __launch_bounds__(256) rst_ln2_kernel(const float* __restrict__ g,
                                                      const float* __restrict__ b) {
    int row = blockIdx.x * 8 + (threadIdx.x >> 5);
    if (row >= Nn) return;
    int lane = threadIdx.x & 31;
    float4 f = ((const float4*)(g_fB + (size_t)row * Dd))[lane];
    float4 h = ((const float4*)(g_h + (size_t)row * Dd))[lane];
    float4 v;
    v.x = f.x + h.x; v.y = f.y + h.y; v.z = f.z + h.z; v.w = f.w + h.w;
    ((float4*)(g_feat0 + (size_t)row * Dd))[lane] = v;  // rst
    float s  = v.x + v.y + v.z + v.w;
    float sq = v.x * v.x + v.y * v.y + v.z * v.z + v.w * v.w;
    #pragma unroll
    for (int o = 16; o; o >>= 1) {
        s  += __shfl_xor_sync(0xffffffffu, s, o);
        sq += __shfl_xor_sync(0xffffffffu, sq, o);
    }
    float mu  = s * (1.0f / Dd);
    float var = sq * (1.0f / Dd) - mu * mu;
    float inv = rsqrtf(var + 1e-5f);
    float4 gg = ((const float4*)g)[lane];
    float4 bb = ((const float4*)b)[lane];
    float4 o4;
    o4.x = (v.x - mu) * inv * gg.x + bb.x;
    o4.y = (v.y - mu) * inv * gg.y + bb.y;
    o4.z = (v.z - mu) * inv * gg.z + bb.z;
    o4.w = (v.w - mu) * inv * gg.w + bb.w;
    ((float4*)(g_fA + (size_t)row * Dd))[lane] = o4;    // x
}

// ---------------- eh/et: one thread per (n, h) ----------------
__global__ void __launch_bounds__(256) ehet_kernel(const float* __restrict__ ah,
                                                   const float* __restrict__ at) {
    int i = blockIdx.x * blockDim.x + threadIdx.x;   // n*8 + h
    if (i >= Nn * Hh) return;
    int h = i & 7;
    const float4* f = (const float4*)(g_feat0 + (size_t)i * 16);
    const float4* wh = (const float4*)(ah + h * 16);
    const float4* wt = (const float4*)(at + h * 16);
    float s1 = 0.f, s2 = 0.f;
    #pragma unroll
    for (int j = 0; j < 4; j++) {
        float4 fv = f[j];
        float4 w1 = wh[j];
        float4 w2 = wt[j];
        s1 += fv.x * w1.x + fv.y * w1.y + fv.z * w1.z + fv.w * w1.w;
        s2 += fv.x * w2.x + fv.y * w2.y + fv.z * w2.z + fv.w * w2.w;
    }
    g_eh[i] = s1;
    g_et[i] = s2;
}

// ---------------- CSR build ----------------
__global__ void zero_cnt_kernel() {
    int i = blockIdx.x * blockDim.x + threadIdx.x;
    if (i < Nn) g_cnt[i] = 0;
}
__global__ void hist_kernel(const int* __restrict__ dst) {
    int e = blockIdx.x * blockDim.x + threadIdx.x;
    if (e < Ee) atomicAdd(&g_cnt[dst[e]], 1);
}
__global__ void scan1_kernel() {
    __shared__ int sh[1024];
    int tid = threadIdx.x;
    int i = blockIdx.x * 1024 + tid;
    int v = (i < Nn) ? g_cnt[i] : 0;
    sh[tid] = v;
    __syncthreads();
    for (int off = 1; off < 1024; off <<= 1) {
        int t = (tid >= off) ? sh[tid - off] : 0;
        __syncthreads();
        sh[tid] += t;
        __syncthreads();
    }
    if (i < Nn) g_rowptr[i] = sh[tid] - v;          // block-local exclusive
    if (tid == 1023) g_bsum[blockIdx.x] = sh[1023];
}
__global__ void scan2_kernel(int nb) {
    __shared__ int sh[128];
    int tid = threadIdx.x;
    int v = (tid < nb) ? g_bsum[tid] : 0;
    sh[tid] = v;
    __syncthreads();
    for (int off = 1; off < 128; off <<= 1) {
        int t = (tid >= off) ? sh[tid - off] : 0;
        __syncthreads();
        sh[tid] += t;
        __syncthreads();
    }
    if (tid < nb) g_bsum[tid] = sh[tid] - v;        // exclusive block offsets
}
__global__ void scan3_kernel() {
    int i = blockIdx.x * 1024 + threadIdx.x;
    if (i < Nn) {
        int r = g_rowptr[i] + g_bsum[blockIdx.x];
        g_rowptr[i] = r;
        g_wptr[i] = r;
    }
    if (i == 0) g_rowptr[Nn] = Ee;
}
__global__ void fill_kernel(const int* __restrict__ dst) {
    int e = blockIdx.x * blockDim.x + threadIdx.x;
    if (e < Ee) {
        int p = atomicAdd(&g_wptr[dst[e]], 1);
        g_csredge[p] = e;
    }
}

// ---------------- edge softmax over CSR rows: warp per node ----------------
__global__ void __launch_bounds__(256) softmax_pack_kernel(const int* __restrict__ src) {
    int n = blockIdx.x * 8 + (threadIdx.x >> 5);
    if (n >= Nn) return;
    int lane = threadIdx.x & 31;
    int h = lane & 7;
    int sub = lane >> 3;
    int r0 = g_rowptr[n], r1 = g_rowptr[n + 1];
    float myet = g_et[n * Hh + h];

    float mx = -1e30f;
    for (int p = r0 + sub; p < r1; p += 4) {
        int e = g_csredge[p];
        int s = src[e];
        float v = g_eh[s * Hh + h] + myet;
        v = v > 0.f ? v : 0.2f * v;
        mx = fmaxf(mx, v);
    }
    mx = fmaxf(mx, __shfl_xor_sync(0xffffffffu, mx, 8));
    mx = fmaxf(mx, __shfl_xor_sync(0xffffffffu, mx, 16));

    float sum = 0.f;
    for (int p = r0 + sub; p < r1; p += 4) {
        int e = g_csredge[p];
        int s = src[e];
        float v = g_eh[s * Hh + h] + myet;
        v = v > 0.f ? v : 0.2f * v;
        sum += expf(v - mx);
    }
    sum += __shfl_xor_sync(0xffffffffu, sum, 8);
    sum += __shfl_xor_sync(0xffffffffu, sum, 16);
    float inv = 1.0f / sum;

    for (int p = r0 + sub; p < r1; p += 4) {
        int e = g_csredge[p];
        int s = src[e];
        float v = g_eh[s * Hh + h] + myet;
        v = v > 0.f ? v : 0.2f * v;
        g_acsr[(size_t)p * Hh + h] = expf(v - mx) * inv;
        if (h == 0) g_srccsr[p] = s;
    }
}

// ---------------- one propagation hop: warp per node ----------------
__global__ void __launch_bounds__(256) hop_kernel(int ini, int outi) {
    int n = blockIdx.x * 8 + (threadIdx.x >> 5);
    if (n >= Nn) return;
    const float* __restrict__ fin = gbuf(ini);
    float* __restrict__ fout = gbuf(outi);
    int lane = threadIdx.x & 31;
    int h = lane >> 2;
    int r0 = g_rowptr[n], r1 = g_rowptr[n + 1];
    float4 acc = make_float4(0.f, 0.f, 0.f, 0.f);
    int p = r0;
    for (; p + 1 < r1; p += 2) {
        int s0 = g_srccsr[p];
        int s1 = g_srccsr[p + 1];
        float w0 = g_acsr[(size_t)p * Hh + h];
        float w1 = g_acsr[(size_t)(p + 1) * Hh + h];
        float4 v0 = *(const float4*)(fin + (size_t)s0 * Dd + lane * 4);
        float4 v1 = *(const float4*)(fin + (size_t)s1 * Dd + lane * 4);
        acc.x += w0 * v0.x; acc.y += w0 * v0.y; acc.z += w0 * v0.z; acc.w += w0 * v0.w;
        acc.x += w1 * v1.x; acc.y += w1 * v1.y; acc.z += w1 * v1.z; acc.w += w1 * v1.w;
    }
    if (p < r1) {
        int s0 = g_srccsr[p];
        float w0 = g_acsr[(size_t)p * Hh + h];
        float4 v0 = *(const float4*)(fin + (size_t)s0 * Dd + lane * 4);
        acc.x += w0 * v0.x; acc.y += w0 * v0.y; acc.z += w0 * v0.z; acc.w += w0 * v0.w;
    }
    float4 f0 = *(const float4*)(g_feat0 + (size_t)n * Dd + lane * 4);
    float4 o;
    o.x = 0.85f * acc.x + 0.15f * f0.x;
    o.y = 0.85f * acc.y + 0.15f * f0.y;
    o.z = 0.85f * acc.z + 0.15f * f0.z;
    o.w = 0.85f * acc.w + 0.15f * f0.w;
    *(float4*)(fout + (size_t)n * Dd + lane * 4) = o;
}

// ---------------- launch ----------------
extern "C" void kernel_launch(void* const* d_in, const int* in_sizes, int n_in,
                              void* d_out, int out_size) {
    const float* ent = (const float*)d_in[0];
    const int*   src = (const int*)d_in[1];
    const int*   dst = (const int*)d_in[2];
    const float* Went = (const float*)d_in[3];
    const float* ah  = (const float*)d_in[4];
    const float* at  = (const float*)d_in[5];
    const float* ln1g = (const float*)d_in[6];
    const float* ln1b = (const float*)d_in[7];
    const float* ln2g = (const float*)d_in[8];
    const float* ln2b = (const float*)d_in[9];
    const float* w1  = (const float*)d_in[10];
    const float* b1  = (const float*)d_in[11];
    const float* w2  = (const float*)d_in[12];
    const float* b2  = (const float*)d_in[13];
    float* out = (float*)d_out;

    const int NWARP_GRID = (Nn + 7) / 8;          // 12500
    const int ROWTILES = (Nn + 127) / 128;        // 782

    ln1_kernel<<<NWARP_GRID, 256>>>(ent, ln1g, ln1b);
    zero_cnt_kernel<<<(Nn + 255) / 256, 256>>>();
    hist_kernel<<<(Ee + 255) / 256, 256>>>(dst);
    // feat0 = h @ W_ent^T   (launch #4 — ncu capture target)
    mgemm_kernel<<<dim3(1, ROWTILES), 256>>>(0, Went, nullptr, -1, 1, nullptr, 128, 128, 0);
    scan1_kernel<<<(Nn + 1023) / 1024, 1024>>>();
    scan2_kernel<<<1, 128>>>((Nn + 1023) / 1024);
    scan3_kernel<<<(Nn + 1023) / 1024, 1024>>>();
    fill_kernel<<<(Ee + 255) / 256, 256>>>(dst);
    ehet_kernel<<<(Nn * Hh + 255) / 256, 256>>>(ah, at);

    softmax_pack_kernel<<<NWARP_GRID, 256>>>(src);

    hop_kernel<<<NWARP_GRID, 256>>>(1, 2);  // feat0 -> fA
    hop_kernel<<<NWARP_GRID, 256>>>(2, 3);  // fA -> fB
    hop_kernel<<<NWARP_GRID, 256>>>(3, 2);
    hop_kernel<<<NWARP_GRID, 256>>>(2, 3);
    hop_kernel<<<NWARP_GRID, 256>>>(3, 2);
    hop_kernel<<<NWARP_GRID, 256>>>(2, 3);  // final in fB

    rst_ln2_kernel<<<NWARP_GRID, 256>>>(ln2g, ln2b);  // rst -> feat0, x -> fA

    // hidden = relu(x @ w1^T + b1)
    mgemm_kernel<<<dim3(4, ROWTILES), 256>>>(2, w1, b1, -1, 4, nullptr, 512, 128, 1);
    // out = hidden @ w2^T + b2 + rst
    mgemm_kernel<<<dim3(1, ROWTILES), 256>>>(4, w2, b2, 1, -1, out, 128, 512, 2);
}

// round 6
// speedup vs baseline: 1.1385x; 1.1385x over previous
#include <cuda_runtime.h>
#include <cstdint>

#define Nn 100000
#define Ee 1600000
#define Dd 128
#define Hh 8
#define FF 512

typedef unsigned long long u64;

// ---------------- scratch (device globals; no allocs allowed) ----------------
__device__ float g_h[Nn * Dd];        // LN1 output
__device__ float g_feat0[Nn * Dd];    // initial feat (GEMM1 out); later rst
__device__ float g_fA[Nn * Dd];       // ping ; later x (LN2 out)
__device__ float g_fB[Nn * Dd];       // pong
__device__ float g_hidden[Nn * FF];   // FFN hidden
__device__ float g_eh[Nn * Hh];
__device__ float g_et[Nn * Hh];
__device__ float g_acsr[Ee * Hh];     // normalized attention, CSR order
__device__ int   g_srccsr[Ee];        // src node per CSR slot
__device__ int   g_csredge[Ee];       // original edge id per CSR slot
__device__ int   g_cnt[Nn];
__device__ int   g_rowptr[Nn + 1];
__device__ int   g_wptr[Nn];
__device__ int   g_bsum[128];

__device__ __forceinline__ float* gbuf(int i) {
    switch (i) {
        case 0: return g_h;
        case 1: return g_feat0;
        case 2: return g_fA;
        case 3: return g_fB;
        case 4: return g_hidden;
    }
    return nullptr;
}

__device__ __forceinline__ void mma_tf32(float& c0, float& c1, float& c2, float& c3,
                                         uint32_t a0, uint32_t a1, uint32_t a2, uint32_t a3,
                                         uint32_t b0, uint32_t b1) {
    asm volatile(
        "mma.sync.aligned.m16n8k8.row.col.f32.tf32.tf32.f32 "
        "{%0,%1,%2,%3}, {%4,%5,%6,%7}, {%8,%9}, {%0,%1,%2,%3};"
        : "+f"(c0), "+f"(c1), "+f"(c2), "+f"(c3)
        : "r"(a0), "r"(a1), "r"(a2), "r"(a3), "r"(b0), "r"(b1));
}

__device__ __forceinline__ void cpasync16(uint32_t s, const void* g, int sz) {
    asm volatile("cp.async.cg.shared.global [%0], [%1], 16, %2;"
                 :: "r"(s), "l"(g), "r"(sz) : "memory");
}
#define CP_COMMIT() asm volatile("cp.async.commit_group;" ::: "memory")
#define CP_WAIT1() asm volatile("cp.async.wait_group 1;" ::: "memory")
#define CP_WAIT0() asm volatile("cp.async.wait_group 0;" ::: "memory")

// load float from smem + truncate to tf32 (round-to-nearest-even on 10-bit mantissa)
__device__ __forceinline__ uint32_t ld_tf(const float* p) {
    unsigned r;
    asm("cvt.rna.tf32.f32 %0, %1;" : "=r"(r) : "f"(*p));
    return r;
}

// swizzled float index into a [128][16] tile (xor on col bits 2..3)
__device__ __forceinline__ int swz(int row, int col) {
    return (row << 4) | (col ^ ((row & 3) << 2));
}

// ---------------- tf32 mma.sync GEMM + cp.async double buffer ----------------
// C[rows x M] = A[rows x K] * B[M x K]^T
// mode 0: plain   mode 1: relu(x + bias)   mode 2: x + bias + add
__global__ void __launch_bounds__(256, 2) mgemm_kernel(int Ai, const float* __restrict__ B,
                                                       const float* __restrict__ bias,
                                                       int Addi, int Ci, float* __restrict__ Cext,
                                                       int M, int K, int mode) {
    __shared__ float As[2][128 * 16];
    __shared__ float Bs[2][128 * 16];
    const float* A = gbuf(Ai);
    float* C = (Ci >= 0) ? gbuf(Ci) : Cext;
    const float* add = (Addi >= 0) ? gbuf(Addi) : nullptr;

    int bm = blockIdx.y * 128;
    int bn = blockIdx.x * 128;
    int tid = threadIdx.x;
    int wid = tid >> 5, lane = tid & 31;
    int g = lane >> 2, t4 = lane & 3;
    int warpM = wid & 3, warpN = wid >> 2;   // 4 x 2 warps

    float acc[2][8][4];
    #pragma unroll
    for (int i = 0; i < 2; i++)
        #pragma unroll
        for (int j = 0; j < 8; j++)
            #pragma unroll
            for (int q = 0; q < 4; q++) acc[i][j][q] = 0.0f;

    // copy mapping: thread -> (row, 8-float half)
    int crow = tid >> 1;
    int c0 = (tid & 1) * 8;
    bool aval = (bm + crow) < Nn;
    const float* agp = A + (size_t)(aval ? (bm + crow) : 0) * K + c0;
    const float* bgp = B + (size_t)(bn + crow) * K + c0;
    int asz = aval ? 16 : 0;

    uint32_t sA = (uint32_t)__cvta_generic_to_shared(As);
    uint32_t sB = (uint32_t)__cvta_generic_to_shared(Bs);
    uint32_t dA0 = sA + (uint32_t)swz(crow, c0) * 4u;
    uint32_t dA1 = sA + (uint32_t)swz(crow, c0 + 4) * 4u;
    uint32_t dB0 = sB + (uint32_t)swz(crow, c0) * 4u;
    uint32_t dB1 = sB + (uint32_t)swz(crow, c0 + 4) * 4u;

    const int nit = K >> 4;
    // prologue: stage 0
    {
        cpasync16(dA0, agp, asz);
        cpasync16(dA1, agp + 4, asz);
        cpasync16(dB0, bgp, 16);
        cpasync16(dB1, bgp + 4, 16);
        CP_COMMIT();
    }

    for (int i = 0; i < nit; i++) {
        if (i + 1 < nit) {
            uint32_t boff = ((i + 1) & 1) * (128 * 16 * 4);
            int kk = (i + 1) << 4;
            cpasync16(dA0 + boff, agp + kk, asz);
            cpasync16(dA1 + boff, agp + kk + 4, asz);
            cpasync16(dB0 + boff, bgp + kk, 16);
            cpasync16(dB1 + boff, bgp + kk + 4, 16);
            CP_COMMIT();
            CP_WAIT1();
        } else {
            CP_WAIT0();
        }
        __syncthreads();
        const float* as = As[i & 1];
        const float* bs = Bs[i & 1];
        #pragma unroll
        for (int k0 = 0; k0 < 16; k0 += 8) {
            uint32_t af[2][4];
            #pragma unroll
            for (int mt = 0; mt < 2; mt++) {
                int m0 = warpM * 32 + mt * 16 + g;
                af[mt][0] = ld_tf(&as[swz(m0, k0 + t4)]);
                af[mt][1] = ld_tf(&as[swz(m0 + 8, k0 + t4)]);
                af[mt][2] = ld_tf(&as[swz(m0, k0 + t4 + 4)]);
                af[mt][3] = ld_tf(&as[swz(m0 + 8, k0 + t4 + 4)]);
            }
            uint32_t bf[8][2];
            #pragma unroll
            for (int nt = 0; nt < 8; nt++) {
                int n0 = warpN * 64 + nt * 8 + g;
                bf[nt][0] = ld_tf(&bs[swz(n0, k0 + t4)]);
                bf[nt][1] = ld_tf(&bs[swz(n0, k0 + t4 + 4)]);
            }
            #pragma unroll
            for (int mt = 0; mt < 2; mt++)
                #pragma unroll
                for (int nt = 0; nt < 8; nt++)
                    mma_tf32(acc[mt][nt][0], acc[mt][nt][1], acc[mt][nt][2], acc[mt][nt][3],
                             af[mt][0], af[mt][1], af[mt][2], af[mt][3],
                             bf[nt][0], bf[nt][1]);
        }
        __syncthreads();
    }

    // ---- epilogue: fragments -> C with fused bias/relu/add
    #pragma unroll
    for (int mt = 0; mt < 2; mt++) {
        int row0 = bm + warpM * 32 + mt * 16 + g;
        #pragma unroll
        for (int half = 0; half < 2; half++) {
            int row = row0 + half * 8;
            if (row >= Nn) continue;
            #pragma unroll
            for (int nt = 0; nt < 8; nt++) {
                int col = bn + warpN * 64 + nt * 8 + t4 * 2;
                float c0 = acc[mt][nt][half * 2];
                float c1 = acc[mt][nt][half * 2 + 1];
                if (mode >= 1) {
                    c0 += bias[col];
                    c1 += bias[col + 1];
                }
                if (mode == 1) {
                    c0 = fmaxf(c0, 0.f);
                    c1 = fmaxf(c1, 0.f);
                }
                if (mode == 2) {
                    const float* av = add + (size_t)row * M + col;
                    c0 += av[0];
                    c1 += av[1];
                }
                *(float2*)(C + (size_t)row * M + col) = make_float2(c0, c1);
            }
        }
    }
}

// ---------------- LN1: warp per row ----------------
__global__ void __launch_bounds__(256) ln1_kernel(const float* __restrict__ x,
                                                  const float* __restrict__ g,
                                                  const float* __restrict__ b) {
    int row = blockIdx.x * 8 + (threadIdx.x >> 5);
    if (row >= Nn) return;
    int lane = threadIdx.x & 31;
    float4 v = ((const float4*)(x + (size_t)row * Dd))[lane];
    float s  = v.x + v.y + v.z + v.w;
    float sq = v.x * v.x + v.y * v.y + v.z * v.z + v.w * v.w;
    #pragma unroll
    for (int o = 16; o; o >>= 1) {
        s  += __shfl_xor_sync(0xffffffffu, s, o);
        sq += __shfl_xor_sync(0xffffffffu, sq, o);
    }
    float mu  = s * (1.0f / Dd);
    float var = sq * (1.0f / Dd) - mu * mu;
    float inv = rsqrtf(var + 1e-5f);
    float4 gg = ((const float4*)g)[lane];
    float4 bb = ((const float4*)b)[lane];
    float4 o4;
    o4.x = (v.x - mu) * inv * gg.x + bb.x;
    o4.y = (v.y - mu) * inv * gg.y + bb.y;
    o4.z = (v.z - mu) * inv * gg.z + bb.z;
    o4.w = (v.w - mu) * inv * gg.w + bb.w;
    ((float4*)(g_h + (size_t)row * Dd))[lane] = o4;
}

// ---------------- rst = feat_final + h ; x = LN2(rst) ----------------
__global__ void __launch_bounds__(256) rst_ln2_kernel(const float* __restrict__ g,
                                                      const float* __restrict__ b) {
    int row = blockIdx.x * 8 + (threadIdx.x >> 5);
    if (row >= Nn) return;
    int lane = threadIdx.x & 31;
    float4 f = ((const float4*)(g_fB + (size_t)row * Dd))[lane];
    float4 h = ((const float4*)(g_h + (size_t)row * Dd))[lane];
    float4 v;
    v.x = f.x + h.x; v.y = f.y + h.y; v.z = f.z + h.z; v.w = f.w + h.w;
    ((float4*)(g_feat0 + (size_t)row * Dd))[lane] = v;  // rst
    float s  = v.x + v.y + v.z + v.w;
    float sq = v.x * v.x + v.y * v.y + v.z * v.z + v.w * v.w;
    #pragma unroll
    for (int o = 16; o; o >>= 1) {
        s  += __shfl_xor_sync(0xffffffffu, s, o);
        sq += __shfl_xor_sync(0xffffffffu, sq, o);
    }
    float mu  = s * (1.0f / Dd);
    float var = sq * (1.0f / Dd) - mu * mu;
    float inv = rsqrtf(var + 1e-5f);
    float4 gg = ((const float4*)g)[lane];
    float4 bb = ((const float4*)b)[lane];
    float4 o4;
    o4.x = (v.x - mu) * inv * gg.x + bb.x;
    o4.y = (v.y - mu) * inv * gg.y + bb.y;
    o4.z = (v.z - mu) * inv * gg.z + bb.z;
    o4.w = (v.w - mu) * inv * gg.w + bb.w;
    ((float4*)(g_fA + (size_t)row * Dd))[lane] = o4;    // x
}

// ---------------- eh/et: one thread per (n, h) ----------------
__global__ void __launch_bounds__(256) ehet_kernel(const float* __restrict__ ah,
                                                   const float* __restrict__ at) {
    int i = blockIdx.x * blockDim.x + threadIdx.x;   // n*8 + h
    if (i >= Nn * Hh) return;
    int h = i & 7;
    const float4* f = (const float4*)(g_feat0 + (size_t)i * 16);
    const float4* wh = (const float4*)(ah + h * 16);
    const float4* wt = (const float4*)(at + h * 16);
    float s1 = 0.f, s2 = 0.f;
    #pragma unroll
    for (int j = 0; j < 4; j++) {
        float4 fv = f[j];
        float4 w1 = wh[j];
        float4 w2 = wt[j];
        s1 += fv.x * w1.x + fv.y * w1.y + fv.z * w1.z + fv.w * w1.w;
        s2 += fv.x * w2.x + fv.y * w2.y + fv.z * w2.z + fv.w * w2.w;
    }
    g_eh[i] = s1;
    g_et[i] = s2;
}

// ---------------- CSR build ----------------
__global__ void zero_cnt_kernel() {
    int i = blockIdx.x * blockDim.x + threadIdx.x;
    if (i < Nn) g_cnt[i] = 0;
}
__global__ void hist_kernel(const int* __restrict__ dst) {
    int e = blockIdx.x * blockDim.x + threadIdx.x;
    if (e < Ee) atomicAdd(&g_cnt[dst[e]], 1);
}
__global__ void scan1_kernel() {
    __shared__ int sh[1024];
    int tid = threadIdx.x;
    int i = blockIdx.x * 1024 + tid;
    int v = (i < Nn) ? g_cnt[i] : 0;
    sh[tid] = v;
    __syncthreads();
    for (int off = 1; off < 1024; off <<= 1) {
        int t = (tid >= off) ? sh[tid - off] : 0;
        __syncthreads();
        sh[tid] += t;
        __syncthreads();
    }
    if (i < Nn) g_rowptr[i] = sh[tid] - v;          // block-local exclusive
    if (tid == 1023) g_bsum[blockIdx.x] = sh[1023];
}
__global__ void scan2_kernel(int nb) {
    __shared__ int sh[128];
    int tid = threadIdx.x;
    int v = (tid < nb) ? g_bsum[tid] : 0;
    sh[tid] = v;
    __syncthreads();
    for (int off = 1; off < 128; off <<= 1) {
        int t = (tid >= off) ? sh[tid - off] : 0;
        __syncthreads();
        sh[tid] += t;
        __syncthreads();
    }
    if (tid < nb) g_bsum[tid] = sh[tid] - v;        // exclusive block offsets
}
__global__ void scan3_kernel() {
    int i = blockIdx.x * 1024 + threadIdx.x;
    if (i < Nn) {
        int r = g_rowptr[i] + g_bsum[blockIdx.x];
        g_rowptr[i] = r;
        g_wptr[i] = r;
    }
    if (i == 0) g_rowptr[Nn] = Ee;
}
__global__ void fill_kernel(const int* __restrict__ dst) {
    int e = blockIdx.x * blockDim.x + threadIdx.x;
    if (e < Ee) {
        int p = atomicAdd(&g_wptr[dst[e]], 1);
        g_csredge[p] = e;
    }
}

// ---------------- edge softmax over CSR rows: warp per node ----------------
__global__ void __launch_bounds__(256) softmax_pack_kernel(const int* __restrict__ src) {
    int n = blockIdx.x * 8 + (threadIdx.x >> 5);
    if (n >= Nn) return;
    int lane = threadIdx.x & 31;
    int h = lane & 7;
    int sub = lane >> 3;
    int r0 = g_rowptr[n], r1 = g_rowptr[n + 1];
    float myet = g_et[n * Hh + h];

    float mx = -1e30f;
    for (int p = r0 + sub; p < r1; p += 4) {
        int e = g_csredge[p];
        int s = src[e];
        float v = g_eh[s * Hh + h] + myet;
        v = v > 0.f ? v : 0.2f * v;
        mx = fmaxf(mx, v);
    }
    mx = fmaxf(mx, __shfl_xor_sync(0xffffffffu, mx, 8));
    mx = fmaxf(mx, __shfl_xor_sync(0xffffffffu, mx, 16));

    float sum = 0.f;
    for (int p = r0 + sub; p < r1; p += 4) {
        int e = g_csredge[p];
        int s = src[e];
        float v = g_eh[s * Hh + h] + myet;
        v = v > 0.f ? v : 0.2f * v;
        sum += expf(v - mx);
    }
    sum += __shfl_xor_sync(0xffffffffu, sum, 8);
    sum += __shfl_xor_sync(0xffffffffu, sum, 16);
    float inv = 1.0f / sum;

    for (int p = r0 + sub; p < r1; p += 4) {
        int e = g_csredge[p];
        int s = src[e];
        float v = g_eh[s * Hh + h] + myet;
        v = v > 0.f ? v : 0.2f * v;
        g_acsr[(size_t)p * Hh + h] = expf(v - mx) * inv;
        if (h == 0) g_srccsr[p] = s;
    }
}

// ---------------- one propagation hop: warp per node ----------------
__global__ void __launch_bounds__(256) hop_kernel(int ini, int outi) {
    int n = blockIdx.x * 8 + (threadIdx.x >> 5);
    if (n >= Nn) return;
    const float* __restrict__ fin = gbuf(ini);
    float* __restrict__ fout = gbuf(outi);
    int lane = threadIdx.x & 31;
    int h = lane >> 2;
    int r0 = g_rowptr[n], r1 = g_rowptr[n + 1];
    float4 acc = make_float4(0.f, 0.f, 0.f, 0.f);
    int p = r0;
    for (; p + 1 < r1; p += 2) {
        int s0 = g_srccsr[p];
        int s1 = g_srccsr[p + 1];
        float w0 = g_acsr[(size_t)p * Hh + h];
        float w1 = g_acsr[(size_t)(p + 1) * Hh + h];
        float4 v0 = *(const float4*)(fin + (size_t)s0 * Dd + lane * 4);
        float4 v1 = *(const float4*)(fin + (size_t)s1 * Dd + lane * 4);
        acc.x += w0 * v0.x; acc.y += w0 * v0.y; acc.z += w0 * v0.z; acc.w += w0 * v0.w;
        acc.x += w1 * v1.x; acc.y += w1 * v1.y; acc.z += w1 * v1.z; acc.w += w1 * v1.w;
    }
    if (p < r1) {
        int s0 = g_srccsr[p];
        float w0 = g_acsr[(size_t)p * Hh + h];
        float4 v0 = *(const float4*)(fin + (size_t)s0 * Dd + lane * 4);
        acc.x += w0 * v0.x; acc.y += w0 * v0.y; acc.z += w0 * v0.z; acc.w += w0 * v0.w;
    }
    float4 f0 = *(const float4*)(g_feat0 + (size_t)n * Dd + lane * 4);
    float4 o;
    o.x = 0.85f * acc.x + 0.15f * f0.x;
    o.y = 0.85f * acc.y + 0.15f * f0.y;
    o.z = 0.85f * acc.z + 0.15f * f0.z;
    o.w = 0.85f * acc.w + 0.15f * f0.w;
    *(float4*)(fout + (size_t)n * Dd + lane * 4) = o;
}

// ---------------- launch ----------------
extern "C" void kernel_launch(void* const* d_in, const int* in_sizes, int n_in,
                              void* d_out, int out_size) {
    const float* ent = (const float*)d_in[0];
    const int*   src = (const int*)d_in[1];
    const int*   dst = (const int*)d_in[2];
    const float* Went = (const float*)d_in[3];
    const float* ah  = (const float*)d_in[4];
    const float* at  = (const float*)d_in[5];
    const float* ln1g = (const float*)d_in[6];
    const float* ln1b = (const float*)d_in[7];
    const float* ln2g = (const float*)d_in[8];
    const float* ln2b = (const float*)d_in[9];
    const float* w1  = (const float*)d_in[10];
    const float* b1  = (const float*)d_in[11];
    const float* w2  = (const float*)d_in[12];
    const float* b2  = (const float*)d_in[13];
    float* out = (float*)d_out;

    const int NWARP_GRID = (Nn + 7) / 8;          // 12500
    const int ROWTILES = (Nn + 127) / 128;        // 782

    ln1_kernel<<<NWARP_GRID, 256>>>(ent, ln1g, ln1b);
    zero_cnt_kernel<<<(Nn + 255) / 256, 256>>>();
    hist_kernel<<<(Ee + 255) / 256, 256>>>(dst);
    // feat0 = h @ W_ent^T   (launch #4 — ncu capture target)
    mgemm_kernel<<<dim3(1, ROWTILES), 256>>>(0, Went, nullptr, -1, 1, nullptr, 128, 128, 0);
    scan1_kernel<<<(Nn + 1023) / 1024, 1024>>>();
    scan2_kernel<<<1, 128>>>((Nn + 1023) / 1024);
    scan3_kernel<<<(Nn + 1023) / 1024, 1024>>>();
    fill_kernel<<<(Ee + 255) / 256, 256>>>(dst);
    ehet_kernel<<<(Nn * Hh + 255) / 256, 256>>>(ah, at);

    softmax_pack_kernel<<<NWARP_GRID, 256>>>(src);

    hop_kernel<<<NWARP_GRID, 256>>>(1, 2);  // feat0 -> fA
    hop_kernel<<<NWARP_GRID, 256>>>(2, 3);  // fA -> fB
    hop_kernel<<<NWARP_GRID, 256>>>(3, 2);
    hop_kernel<<<NWARP_GRID, 256>>>(2, 3);
    hop_kernel<<<NWARP_GRID, 256>>>(3, 2);
    hop_kernel<<<NWARP_GRID, 256>>>(2, 3);  // final in fB

    rst_ln2_kernel<<<NWARP_GRID, 256>>>(ln2g, ln2b);  // rst -> feat0, x -> fA

    // hidden = relu(x @ w1^T + b1)
    mgemm_kernel<<<dim3(4, ROWTILES), 256>>>(2, w1, b1, -1, 4, nullptr, 512, 128, 1);
    // out = hidden @ w2^T + b2 + rst
    mgemm_kernel<<<dim3(1, ROWTILES), 256>>>(4, w2, b2, 1, -1, out, 128, 512, 2);
}